// round 12
// baseline (speedup 1.0000x reference)
#include <cuda_runtime.h>
#include <cuda_bf16.h>
#include <cstdint>

// ChamferLoss: B=128, N=M=1024, 3D points (float4, channel 0 unused).
// Single-pass fused: block = (batch, rowchunk<2, colchunk<4), 512 rows x 256
// cols (RPT=4). Each distance computed ONCE feeds BOTH directions: row-min in
// registers, col-min via redux.sync.min.s32 (positive float bits int-ordered).
// Partials stored with plain STG. The 8th block of each batch (atomic ticket)
// becomes the finisher: resolves both directions for that batch, sqrt+sum,
// accumulates into g_accum; the 128th finisher writes out[0] and resets all
// device globals so every graph replay starts clean.

#define BATCHES   128
#define NPTS      1024
#define THREADS   128
#define RPT       4
#define ROWS_PER_BLOCK (THREADS * RPT)        // 512
#define ROWCHUNKS (NPTS / ROWS_PER_BLOCK)     // 2
#define COLCHUNKS 4
#define COLS_PER_BLOCK (NPTS / COLCHUNKS)     // 256
#define NGROUPS_B (COLS_PER_BLOCK / 2)        // 128 packed column pairs
#define BLOCKS_PER_BATCH (ROWCHUNKS * COLCHUNKS)      // 8
#define MAINGRID  (BATCHES * BLOCKS_PER_BATCH)        // 1024

__device__ int g_colmin_part[BATCHES * ROWCHUNKS * NPTS];  // [b][rowchunk][col]
__device__ int g_rowmin_part[BATCHES * COLCHUNKS * NPTS];  // [b][colchunk][row]
__device__ unsigned g_batch_cnt[BATCHES];   // zero-init; finisher restores 0
__device__ float    g_accum;                // zero-init; last finisher restores
__device__ unsigned g_done;                 // zero-init; last finisher restores

__device__ __forceinline__ unsigned long long pack2(float a, float b) {
    unsigned long long r;
    asm("mov.b64 %0, {%1, %2};" : "=l"(r) : "f"(a), "f"(b));
    return r;
}
__device__ __forceinline__ void unpack2(unsigned long long v, float& a, float& b) {
    asm("mov.b64 {%0, %1}, %2;" : "=f"(a), "=f"(b) : "l"(v));
}
__device__ __forceinline__ unsigned long long add2(unsigned long long a, unsigned long long b) {
    unsigned long long d;
    asm("add.rn.f32x2 %0, %1, %2;" : "=l"(d) : "l"(a), "l"(b));
    return d;
}
__device__ __forceinline__ unsigned long long fma2(unsigned long long a, unsigned long long b,
                                                   unsigned long long c) {
    unsigned long long d;
    asm("fma.rn.f32x2 %0, %1, %2, %3;" : "=l"(d) : "l"(a), "l"(b), "l"(c));
    return d;
}

__global__ void __launch_bounds__(THREADS)
chamfer_main_kernel(const float4* __restrict__ p, const float4* __restrict__ q,
                    float* __restrict__ out) {
    __shared__ unsigned long long sq[(NGROUPS_B + 1) * 4];
    __shared__ int colmin_w[4 * COLS_PER_BLOCK];
    __shared__ float warp_sums[4];
    __shared__ int ticket_s;

    const int bid      = blockIdx.x;
    const int colchunk = bid & (COLCHUNKS - 1);
    const int rowchunk = (bid >> 2) & (ROWCHUNKS - 1);
    const int b        = bid >> 3;
    const int tid      = threadIdx.x;
    const int wid      = tid >> 5;
    const int lid      = tid & 31;

    const float4* rowpts = p + b * NPTS;
    const float4* colpts = q + b * NPTS + colchunk * COLS_PER_BLOCK;

    // ---- Fill packed column smem (qn pre-biased by +1) ----
    #pragma unroll
    for (int i = tid; i < NGROUPS_B; i += THREADS) {
        float4 P0 = colpts[2 * i];
        float4 P1 = colpts[2 * i + 1];
        float n0 = P0.y * P0.y + P0.z * P0.z + P0.w * P0.w + 1.0f;
        float n1 = P1.y * P1.y + P1.z * P1.z + P1.w * P1.w + 1.0f;
        sq[4 * i + 0] = pack2(P0.y, P1.y);
        sq[4 * i + 1] = pack2(P0.z, P1.z);
        sq[4 * i + 2] = pack2(P0.w, P1.w);
        sq[4 * i + 3] = pack2(n0, n1);
    }
    if (tid < 4) sq[4 * NGROUPS_B + tid] = 0;   // prefetch padding

    // ---- This thread's RPT p-rows, coords pre-scaled by -2, pn pre-packed ----
    unsigned long long cx[RPT], cy[RPT], cz[RPT], pn2[RPT];
    #pragma unroll
    for (int k = 0; k < RPT; k++) {
        int r = rowchunk * ROWS_PER_BLOCK + k * THREADS + tid;
        float4 RP = rowpts[r];
        float pnk = RP.y * RP.y + RP.z * RP.z + RP.w * RP.w;
        cx[k] = pack2(-2.0f * RP.y, -2.0f * RP.y);
        cy[k] = pack2(-2.0f * RP.z, -2.0f * RP.z);
        cz[k] = pack2(-2.0f * RP.w, -2.0f * RP.w);
        pn2[k] = pack2(pnk, pnk);
    }

    __syncthreads();

    float rma[RPT], rmb[RPT];
    #pragma unroll
    for (int k = 0; k < RPT; k++) { rma[k] = 3.4e38f; rmb[k] = 3.4e38f; }

    const ulonglong2* sq2 = (const ulonglong2*)sq;
    int* cw = colmin_w + wid * COLS_PER_BLOCK;

    ulonglong2 u01 = sq2[0];
    ulonglong2 u23 = sq2[1];

    #pragma unroll 4
    for (int j = 0; j < NGROUPS_B; j++) {
        ulonglong2 n01 = sq2[2 * (j + 1)];
        ulonglong2 n23 = sq2[2 * (j + 1) + 1];

        float t0[RPT], t1[RPT];
        #pragma unroll
        for (int k = 0; k < RPT; k++) {
            // s = (pn + qn + 1) - 2*dot  -> strictly positive
            unsigned long long s = add2(u23.y, pn2[k]);
            s = fma2(cx[k], u01.x, s);
            s = fma2(cy[k], u01.y, s);
            s = fma2(cz[k], u23.x, s);
            unpack2(s, t0[k], t1[k]);
            rma[k] = fminf(rma[k], t0[k]);
            rmb[k] = fminf(rmb[k], t1[k]);
        }

        float c0f = fminf(fminf(t0[0], t0[1]), fminf(t0[2], t0[3]));
        float c1f = fminf(fminf(t1[0], t1[1]), fminf(t1[2], t1[3]));
        int c0 = __reduce_min_sync(0xFFFFFFFFu, __float_as_int(c0f));
        int c1 = __reduce_min_sync(0xFFFFFFFFu, __float_as_int(c1f));
        if (lid == 0) *(int2*)&cw[2 * j] = make_int2(c0, c1);

        u01 = n01;
        u23 = n23;
    }

    __syncthreads();

    // ---- Col-min: combine 4 warps, store per-(b,rowchunk) partials ----
    int* gcol = g_colmin_part + (b * ROWCHUNKS + rowchunk) * NPTS
                              + colchunk * COLS_PER_BLOCK;
    #pragma unroll
    for (int c = tid; c < COLS_PER_BLOCK; c += THREADS) {
        int m = min(min(colmin_w[c],                      colmin_w[COLS_PER_BLOCK + c]),
                    min(colmin_w[2 * COLS_PER_BLOCK + c], colmin_w[3 * COLS_PER_BLOCK + c]));
        gcol[c] = m;
    }

    // ---- Row-min partials: store per-(b,colchunk) ----
    int* grow = g_rowmin_part + (b * COLCHUNKS + colchunk) * NPTS
                              + rowchunk * ROWS_PER_BLOCK;
    #pragma unroll
    for (int k = 0; k < RPT; k++) {
        float rm = fminf(rma[k], rmb[k]);
        grow[k * THREADS + tid] = __float_as_int(rm);
    }

    // ---- Ticket: 8th arriver for this batch becomes the finisher ----
    __threadfence();
    __syncthreads();
    if (tid == 0) ticket_s = (int)atomicAdd(&g_batch_cnt[b], 1u);
    __syncthreads();
    if (ticket_s != BLOCKS_PER_BATCH - 1) return;

    __threadfence();   // acquire: other blocks' partials now visible

    // ---- Finisher: resolve both directions for batch b, sqrt + sum ----
    const int* rp_base = g_rowmin_part + b * COLCHUNKS * NPTS;
    const int* cp_base = g_colmin_part + b * ROWCHUNKS * NPTS;
    float bsum = 0.0f;
    #pragma unroll
    for (int i = tid; i < NPTS; i += THREADS) {
        int mr = min(min(__ldcg(rp_base + i),            __ldcg(rp_base + NPTS + i)),
                     min(__ldcg(rp_base + 2 * NPTS + i), __ldcg(rp_base + 3 * NPTS + i)));
        int mc = min(__ldcg(cp_base + i), __ldcg(cp_base + NPTS + i));
        float dr = __int_as_float(mr) - 1.0f;
        float dc = __int_as_float(mc) - 1.0f;
        bsum += sqrtf(fmaxf(dr, 0.0f) + 1e-16f)
              + sqrtf(fmaxf(dc, 0.0f) + 1e-16f);
    }

    #pragma unroll
    for (int off = 16; off > 0; off >>= 1)
        bsum += __shfl_xor_sync(0xFFFFFFFFu, bsum, off);
    if (lid == 0) warp_sums[wid] = bsum;
    __syncthreads();

    if (tid == 0) {
        float total = 0.5f * (warp_sums[0] + warp_sums[1] + warp_sums[2] + warp_sums[3]);
        g_batch_cnt[b] = 0;                 // restore for next replay
        atomicAdd(&g_accum, total);
        __threadfence();
        unsigned od = atomicAdd(&g_done, 1u);
        if (od == BATCHES - 1) {            // last finisher across all batches
            __threadfence();
            out[0] = *((volatile float*)&g_accum);
            g_accum = 0.0f;                 // restore globals for next replay
            g_done = 0u;
            __threadfence();
        }
    }
}

extern "C" void kernel_launch(void* const* d_in, const int* in_sizes, int n_in,
                              void* d_out, int out_size) {
    const float4* p = (const float4*)d_in[0];
    const float4* q = (const float4*)d_in[1];
    float* out = (float*)d_out;

    chamfer_main_kernel<<<MAINGRID, THREADS>>>(p, q, out);
}

// round 15
// speedup vs baseline: 1.1917x; 1.1917x over previous
#include <cuda_runtime.h>
#include <cuda_bf16.h>
#include <cstdint>

// ChamferLoss: B=128, N=M=1024, 3D points (float4, channel 0 unused).
// Single-pass, 2D-tiled: block = (batch, rowchunk<2, colchunk<4) covering
// 512 rows x 256 cols (RPT=4 rows/thread). Each distance computed ONCE feeds
// BOTH directions: row-min in registers, col-min via one redux.sync.min.s32
// per column (positive float bits are int-ordered). Partial mins stored with
// plain STG; vectorized final kernel (int4 loads, 4 indices/thread) resolves
// both directions and sums. dist_sq+1 = (pn + (qn+1)) - 2*dot via f32x2.

#define BATCHES   128
#define NPTS      1024
#define THREADS   128
#define RPT       4
#define ROWS_PER_BLOCK (THREADS * RPT)        // 512
#define ROWCHUNKS (NPTS / ROWS_PER_BLOCK)     // 2
#define COLCHUNKS 4
#define COLS_PER_BLOCK (NPTS / COLCHUNKS)     // 256
#define NGROUPS_B (COLS_PER_BLOCK / 2)        // 128 packed column pairs
#define MAINGRID  (BATCHES * ROWCHUNKS * COLCHUNKS)   // 1024

__device__ int g_colmin_part[BATCHES * ROWCHUNKS * NPTS];  // [b][rowchunk][col]
__device__ int g_rowmin_part[BATCHES * COLCHUNKS * NPTS];  // [b][colchunk][row]

__device__ __forceinline__ unsigned long long pack2(float a, float b) {
    unsigned long long r;
    asm("mov.b64 %0, {%1, %2};" : "=l"(r) : "f"(a), "f"(b));
    return r;
}
__device__ __forceinline__ void unpack2(unsigned long long v, float& a, float& b) {
    asm("mov.b64 {%0, %1}, %2;" : "=f"(a), "=f"(b) : "l"(v));
}
__device__ __forceinline__ unsigned long long add2(unsigned long long a, unsigned long long b) {
    unsigned long long d;
    asm("add.rn.f32x2 %0, %1, %2;" : "=l"(d) : "l"(a), "l"(b));
    return d;
}
__device__ __forceinline__ unsigned long long fma2(unsigned long long a, unsigned long long b,
                                                   unsigned long long c) {
    unsigned long long d;
    asm("fma.rn.f32x2 %0, %1, %2, %3;" : "=l"(d) : "l"(a), "l"(b), "l"(c));
    return d;
}

__global__ void __launch_bounds__(THREADS)
chamfer_main_kernel(const float4* __restrict__ p, const float4* __restrict__ q,
                    float* __restrict__ out) {
    // Packed column data: group j = q-points (base+2j, base+2j+1):
    //   sq[4j+0]=(y0,y1) sq[4j+1]=(z0,z1) sq[4j+2]=(w0,w1) sq[4j+3]=(qn0+1,qn1+1)
    __shared__ unsigned long long sq[(NGROUPS_B + 1) * 4];
    __shared__ int colmin_w[4 * COLS_PER_BLOCK];   // per-warp col-min bits

    const int bid      = blockIdx.x;
    const int colchunk = bid & (COLCHUNKS - 1);
    const int rowchunk = (bid >> 2) & (ROWCHUNKS - 1);
    const int b        = bid >> 3;
    const int tid      = threadIdx.x;
    const int wid      = tid >> 5;
    const int lid      = tid & 31;

    if (bid == 0 && tid == 0) out[0] = 0.0f;   // stream-ordered before final

    const float4* rowpts = p + b * NPTS;
    const float4* colpts = q + b * NPTS + colchunk * COLS_PER_BLOCK;

    // ---- Fill packed column smem (qn pre-biased by +1) ----
    #pragma unroll
    for (int i = tid; i < NGROUPS_B; i += THREADS) {
        float4 P0 = colpts[2 * i];
        float4 P1 = colpts[2 * i + 1];
        float n0 = P0.y * P0.y + P0.z * P0.z + P0.w * P0.w + 1.0f;
        float n1 = P1.y * P1.y + P1.z * P1.z + P1.w * P1.w + 1.0f;
        sq[4 * i + 0] = pack2(P0.y, P1.y);
        sq[4 * i + 1] = pack2(P0.z, P1.z);
        sq[4 * i + 2] = pack2(P0.w, P1.w);
        sq[4 * i + 3] = pack2(n0, n1);
    }
    if (tid < 4) sq[4 * NGROUPS_B + tid] = 0;   // prefetch padding

    // ---- This thread's RPT p-rows, coords pre-scaled by -2, pn pre-packed ----
    unsigned long long cx[RPT], cy[RPT], cz[RPT], pn2[RPT];
    #pragma unroll
    for (int k = 0; k < RPT; k++) {
        int r = rowchunk * ROWS_PER_BLOCK + k * THREADS + tid;
        float4 RP = rowpts[r];
        float pnk = RP.y * RP.y + RP.z * RP.z + RP.w * RP.w;
        cx[k] = pack2(-2.0f * RP.y, -2.0f * RP.y);
        cy[k] = pack2(-2.0f * RP.z, -2.0f * RP.z);
        cz[k] = pack2(-2.0f * RP.w, -2.0f * RP.w);
        pn2[k] = pack2(pnk, pnk);
    }

    __syncthreads();

    float rma[RPT], rmb[RPT];
    #pragma unroll
    for (int k = 0; k < RPT; k++) { rma[k] = 3.4e38f; rmb[k] = 3.4e38f; }

    const ulonglong2* sq2 = (const ulonglong2*)sq;
    int* cw = colmin_w + wid * COLS_PER_BLOCK;

    ulonglong2 u01 = sq2[0];
    ulonglong2 u23 = sq2[1];

    #pragma unroll 4
    for (int j = 0; j < NGROUPS_B; j++) {
        ulonglong2 n01 = sq2[2 * (j + 1)];
        ulonglong2 n23 = sq2[2 * (j + 1) + 1];

        float t0[RPT], t1[RPT];
        #pragma unroll
        for (int k = 0; k < RPT; k++) {
            // s = (pn + qn + 1) - 2*dot  -> strictly positive
            unsigned long long s = add2(u23.y, pn2[k]);
            s = fma2(cx[k], u01.x, s);
            s = fma2(cy[k], u01.y, s);
            s = fma2(cz[k], u23.x, s);
            unpack2(s, t0[k], t1[k]);
            rma[k] = fminf(rma[k], t0[k]);     // row-min partials
            rmb[k] = fminf(rmb[k], t1[k]);
        }

        // col-min: 2-level tree over this lane's 4 rows, then across 32 lanes
        float c0f = fminf(fminf(t0[0], t0[1]), fminf(t0[2], t0[3]));
        float c1f = fminf(fminf(t1[0], t1[1]), fminf(t1[2], t1[3]));
        int c0 = __reduce_min_sync(0xFFFFFFFFu, __float_as_int(c0f));
        int c1 = __reduce_min_sync(0xFFFFFFFFu, __float_as_int(c1f));
        if (lid == 0) *(int2*)&cw[2 * j] = make_int2(c0, c1);

        u01 = n01;
        u23 = n23;
    }

    __syncthreads();

    // ---- Col-min: combine 4 warps, plain store to per-(b,rowchunk) partials ----
    int* gcol = g_colmin_part + (b * ROWCHUNKS + rowchunk) * NPTS
                              + colchunk * COLS_PER_BLOCK;
    #pragma unroll
    for (int c = tid; c < COLS_PER_BLOCK; c += THREADS) {
        int m = min(min(colmin_w[c],                      colmin_w[COLS_PER_BLOCK + c]),
                    min(colmin_w[2 * COLS_PER_BLOCK + c], colmin_w[3 * COLS_PER_BLOCK + c]));
        gcol[c] = m;
    }

    // ---- Row-min partials: plain store per (b, colchunk) ----
    int* grow = g_rowmin_part + (b * COLCHUNKS + colchunk) * NPTS
                              + rowchunk * ROWS_PER_BLOCK;
    #pragma unroll
    for (int k = 0; k < RPT; k++) {
        float rm = fminf(rma[k], rmb[k]);
        grow[k * THREADS + tid] = __float_as_int(rm);
    }
}

__device__ __forceinline__ int4 min4(int4 a, int4 b) {
    return make_int4(min(a.x, b.x), min(a.y, b.y), min(a.z, b.z), min(a.w, b.w));
}

__global__ void __launch_bounds__(256)
chamfer_final_kernel(float* __restrict__ out) {
    __shared__ float wsums[8];
    // Each thread resolves 4 consecutive indices: 6 independent int4 loads.
    int t    = blockIdx.x * 256 + threadIdx.x;   // 32768 threads
    int idx4 = t * 4;                            // over BATCHES*NPTS
    int b    = idx4 >> 10;
    int i    = idx4 & (NPTS - 1);

    const int4* rp = (const int4*)(g_rowmin_part + b * COLCHUNKS * NPTS + i);
    const int4* cp = (const int4*)(g_colmin_part + b * ROWCHUNKS * NPTS + i);
    const int STRIDE4 = NPTS / 4;

    int4 r0 = rp[0];
    int4 r1 = rp[STRIDE4];
    int4 r2 = rp[2 * STRIDE4];
    int4 r3 = rp[3 * STRIDE4];
    int4 c0 = cp[0];
    int4 c1 = cp[STRIDE4];

    int4 mr = min4(min4(r0, r1), min4(r2, r3));   // p-side mins (4 rows)
    int4 mc = min4(c0, c1);                       // q-side mins (4 cols)

    float local = 0.0f;
    {
        const int* mri = (const int*)&mr;
        const int* mci = (const int*)&mc;
        #pragma unroll
        for (int k = 0; k < 4; k++) {
            float dr = __int_as_float(mri[k]) - 1.0f;
            float dc = __int_as_float(mci[k]) - 1.0f;
            local += sqrtf(fmaxf(dr, 0.0f) + 1e-16f)
                   + sqrtf(fmaxf(dc, 0.0f) + 1e-16f);
        }
    }

    #pragma unroll
    for (int off = 16; off > 0; off >>= 1)
        local += __shfl_xor_sync(0xFFFFFFFFu, local, off);
    int wid = threadIdx.x >> 5, lid = threadIdx.x & 31;
    if (lid == 0) wsums[wid] = local;
    __syncthreads();
    if (wid == 0) {
        float s = (lid < 8) ? wsums[lid] : 0.0f;
        #pragma unroll
        for (int off = 4; off > 0; off >>= 1)
            s += __shfl_xor_sync(0xFFFFFFFFu, s, off);
        if (lid == 0) atomicAdd(out, 0.5f * s);
    }
}

extern "C" void kernel_launch(void* const* d_in, const int* in_sizes, int n_in,
                              void* d_out, int out_size) {
    const float4* p = (const float4*)d_in[0];
    const float4* q = (const float4*)d_in[1];
    float* out = (float*)d_out;

    chamfer_main_kernel<<<MAINGRID, THREADS>>>(p, q, out);
    chamfer_final_kernel<<<(BATCHES * NPTS) / (256 * 4), 256>>>(out);
}